// round 17
// baseline (speedup 1.0000x reference)
#include <cuda_runtime.h>
#include <cstdint>
#include <cstdio>

#define TSTEPS 4096
#define NTT    4095
#define VDIM   88
#define HDIM   512
#define RDIM   512
#define GS     20

typedef unsigned long long ull;

// ---------------------------------------------------------------------------
// Scratch (static device globals — no runtime allocation allowed)
// ---------------------------------------------------------------------------
__device__ float  g_a    [NTT * RDIM];
__device__ float  g_uprev[NTT * RDIM];
__device__ float  g_bht  [NTT * HDIM];
__device__ float  g_bvt  [NTT * VDIM];
__device__ double g_ce   [256];
__device__ double g_n2uv [64];
__device__ double g_n2uh [64];

// ---------------------------------------------------------------------------
// Helpers: packed fp32x2 ops (componentwise IEEE fp32 — order-preserving)
// ---------------------------------------------------------------------------
__device__ __forceinline__ ull fma2_(ull a, ull b, ull c) {
    ull d; asm("fma.rn.f32x2 %0, %1, %2, %3;" : "=l"(d) : "l"(a), "l"(b), "l"(c));
    return d;
}
__device__ __forceinline__ ull add2_(ull a, ull b) {
    ull d; asm("add.rn.f32x2 %0, %1, %2;" : "=l"(d) : "l"(a), "l"(b));
    return d;
}
__device__ __forceinline__ ull pack2_(float lo, float hi) {
    ull d; asm("mov.b64 %0, {%1, %2};" : "=l"(d) : "f"(lo), "f"(hi));
    return d;
}
__device__ __forceinline__ ull dup2_(float v) {
    ull d; asm("mov.b64 %0, {%1, %1};" : "=l"(d) : "f"(v));
    return d;
}
__device__ __forceinline__ float lo2_(ull v) { return __uint_as_float((unsigned)v); }
__device__ __forceinline__ float hi2_(ull v) { return __uint_as_float((unsigned)(v >> 32)); }

__device__ __forceinline__ void cluster_sync_() {
    asm volatile("barrier.cluster.arrive.aligned;\n\t"
                 "barrier.cluster.wait.aligned;" ::: "memory");
}
__device__ __forceinline__ uint32_t smem_u32(const void* p) {
    return (uint32_t)__cvta_generic_to_shared(p);
}

// ---------------------------------------------------------------------------
// NT GEMM (proven): C = A*B^T + bias[n]. Stages 1 and 3 only.
// ---------------------------------------------------------------------------
template <int TM>
__global__ void __launch_bounds__(256, 2) gemm2_nt(
    const float* __restrict__ A, int lda,
    const float* __restrict__ B, int ldb,
    const float* __restrict__ bias,
    float* __restrict__ C, int ldc,
    int M, int N, int K)
{
    constexpr int BM  = 16 * TM;
    constexpr int KW  = TM;
    constexpr int TPR = 16 / KW;
    constexpr int AQ  = KW / 4;

    __shared__ __align__(16) float As[16][BM];
    __shared__ __align__(16) float Bs[16][64];

    const int tid = threadIdx.x;
    const int tx  = tid & 15;
    const int ty  = tid >> 4;
    const int m0  = blockIdx.x * BM;
    const int n0  = blockIdx.y * 64;

    const int arow  = tid / TPR;
    const int akb   = (tid % TPR) * KW;
    const int am    = m0 + arow;
    const bool amok = (am < M);
    const int brow  = tid >> 2;
    const int bkb   = (tid & 3) * 4;
    const int bn    = n0 + brow;
    const bool bnok = (bn < N);

    const float* Abase = A + (size_t)am * lda;
    const float* Bbase = B + (size_t)bn * ldb;
    const float4 z4 = make_float4(0.f, 0.f, 0.f, 0.f);

    float4 aR[AQ], bR;
#pragma unroll
    for (int q = 0; q < AQ; q++) {
        int k = akb + q * 4;
        aR[q] = (amok && k < K) ? *(const float4*)(Abase + k) : z4;
    }
    bR = (bnok && bkb < K) ? *(const float4*)(Bbase + bkb) : z4;

    ull acc[TM / 2][4];
#pragma unroll
    for (int i = 0; i < TM / 2; i++)
#pragma unroll
        for (int j = 0; j < 4; j++) acc[i][j] = 0ull;

    for (int k0 = 0; k0 < K; k0 += 16) {
#pragma unroll
        for (int q = 0; q < AQ; q++) {
            As[akb + q * 4 + 0][arow] = aR[q].x;
            As[akb + q * 4 + 1][arow] = aR[q].y;
            As[akb + q * 4 + 2][arow] = aR[q].z;
            As[akb + q * 4 + 3][arow] = aR[q].w;
        }
        Bs[bkb + 0][brow] = bR.x;
        Bs[bkb + 1][brow] = bR.y;
        Bs[bkb + 2][brow] = bR.z;
        Bs[bkb + 3][brow] = bR.w;
        __syncthreads();

        const int kn = k0 + 16;
        if (kn < K) {
#pragma unroll
            for (int q = 0; q < AQ; q++) {
                int k = kn + akb + q * 4;
                aR[q] = (amok && k < K) ? *(const float4*)(Abase + k) : z4;
            }
            int kb = kn + bkb;
            bR = (bnok && kb < K) ? *(const float4*)(Bbase + kb) : z4;
        }

#pragma unroll
        for (int k = 0; k < 16; k++) {
            float4 b4 = *(const float4*)&Bs[k][tx * 4];
            ull bb[4];
            bb[0] = dup2_(b4.x); bb[1] = dup2_(b4.y);
            bb[2] = dup2_(b4.z); bb[3] = dup2_(b4.w);
#pragma unroll
            for (int q = 0; q < TM / 4; q++) {
                ulonglong2 aa = *(const ulonglong2*)&As[k][ty * TM + q * 4];
#pragma unroll
                for (int c = 0; c < 4; c++) {
                    acc[2 * q + 0][c] = fma2_(aa.x, bb[c], acc[2 * q + 0][c]);
                    acc[2 * q + 1][c] = fma2_(aa.y, bb[c], acc[2 * q + 1][c]);
                }
            }
        }
        __syncthreads();
    }

#pragma unroll
    for (int i = 0; i < TM / 2; i++) {
#pragma unroll
        for (int half = 0; half < 2; half++) {
            const int m = m0 + ty * TM + 2 * i + half;
            if (m >= M) continue;
#pragma unroll
            for (int c = 0; c < 4; c++) {
                const int n = n0 + tx * 4 + c;
                if (n >= N) continue;
                float v = half ? hi2_(acc[i][c]) : lo2_(acc[i][c]);
                C[(size_t)m * ldc + n] = v + bias[n];
            }
        }
    }
}

// ---------------------------------------------------------------------------
// Sequential u recurrence (proven math). One change: writeback spread —
// after the full butterfly every lane holds all 4 sums, so 32 lanes issue
// 1 remote DSMEM store each (lane = output (l&3) to rank (l>>2)) instead of
// 4 lanes issuing 8 serial stores. Values per output identical.
// ---------------------------------------------------------------------------
__global__ void __cluster_dims__(8, 1, 1) __launch_bounds__(512, 1)
recur_kernel(const float* __restrict__ wuu, const float* __restrict__ a,
             const float* __restrict__ u0, float* __restrict__ uprev)
{
    __shared__ __align__(16) ull u_d[2][RDIM];

    unsigned rank;
    asm("mov.u32 %0, %%cluster_ctarank;" : "=r"(rank));

    const int tid = threadIdx.x;
    const int w = tid >> 5, l = tid & 31;
    const int obase = (int)rank * 64 + w * 4;

    ull w01[16], w23[16];
#pragma unroll
    for (int j = 0; j < 16; j++) {
        w01[j] = pack2_(wuu[(obase + 0) * RDIM + l + 32 * j],
                        wuu[(obase + 1) * RDIM + l + 32 * j]);
        w23[j] = pack2_(wuu[(obase + 2) * RDIM + l + 32 * j],
                        wuu[(obase + 3) * RDIM + l + 32 * j]);
    }

    {
        float ui = u0[tid];
        u_d[0][tid] = dup2_(ui);
        if (rank == 0) uprev[tid] = ui;
    }

    const uint32_t base0 = smem_u32(&u_d[0][0]);
    const uint32_t base1 = smem_u32(&u_d[1][0]);
    const int o  = l & 3;          // output owned in writeback
    const unsigned rr = l >> 2;    // destination rank in writeback

    cluster_sync_();

    int p = 0;
    for (int t = 0; t < NTT - 1; t++) {
        float av = a[(size_t)t * RDIM + obase + o];

        const ull* us = u_d[p];
        ull s01 = 0ull, s23 = 0ull;
#pragma unroll
        for (int j = 0; j < 16; j++) {
            ull up = us[l + 32 * j];
            s01 = fma2_(w01[j], up, s01);
            s23 = fma2_(w23[j], up, s23);
        }
#pragma unroll
        for (int off = 16; off; off >>= 1) {
            s01 = add2_(s01, __shfl_xor_sync(0xffffffffu, s01, off));
            s23 = add2_(s23, __shfl_xor_sync(0xffffffffu, s23, off));
        }
        {
            float acc = (o == 0) ? lo2_(s01) : (o == 1) ? hi2_(s01)
                      : (o == 2) ? lo2_(s23) : hi2_(s23);
            float un = tanhf(acc + av);
            ull und = dup2_(un);
            uint32_t dst = (p ? base0 : base1) + 8u * (uint32_t)(obase + o);
            uint32_t rem;
            asm volatile("mapa.shared::cluster.u32 %0, %1, %2;"
                         : "=r"(rem) : "r"(dst), "r"(rr));
            asm volatile("st.shared::cluster.b64 [%0], %1;"
                         :: "r"(rem), "l"(und) : "memory");
            if (l < 4) uprev[(size_t)(t + 1) * RDIM + obase + o] = un;
        }
        cluster_sync_();
        p ^= 1;
    }
}

// ---------------------------------------------------------------------------
// Fused sparse/dense Gibbs kernel (bit-exact vs the dense fmaf chain):
//  h-phase: dense ascending-k FFMA2 over (row0,row1)/(row2,row3) packed v
//           floats — fma(0,w,acc)=acc exactly, so == sparse == original.
//  v-phase: sparse h-list walk with add.rn.f32x2 over column pairs
//           (i, i+1) — per-component ascending-j order unchanged.
// w in smem at pitch 92 (float4-aligned, conflict-free both phases).
// ---------------------------------------------------------------------------
#define ROWS_PER_CTA 28
#define WPITCH   92
#define W_FLOATS (512 * WPITCH + WPITCH)   // + zeroed pad row
#define PAD_HOFF (512 * WPITCH * 4)        // byte offset of pad row

__global__ void __launch_bounds__(512, 1) gibbs_fused(
    const float* __restrict__ visible,
    const float* __restrict__ rand_h,
    const float* __restrict__ rand_v,
    const float* __restrict__ w,       // [512][88]
    const float* __restrict__ bht_g,   // [NTT][512]
    const float* __restrict__ bvt_g,   // [NTT][88]
    float* __restrict__ out)           // mse -> out[1 + row]
{
    extern __shared__ __align__(16) char smraw[];
    float*    w_s    = (float*)smraw;                    // W_FLOATS
    float*    bht_s  = w_s + W_FLOATS;                   // 4*512
    float*    bvt_s  = bht_s + 4 * 512;                  // 4*96
    ull*      v01    = (ull*)(bvt_s + 4 * 96);           // 96 (rows 0,1 packed)
    ull*      v23    = v01 + 96;                         // 96 (rows 2,3 packed)
    int*      h_list = (int*)(v23 + 96);                 // 4*520
    unsigned* h_cnt  = (unsigned*)(h_list + 4 * 520);    // 4
    unsigned* vis_w  = h_cnt + 4;                        // 12
    unsigned* h_words= vis_w + 12;                       // 64
    unsigned char* vb = (unsigned char*)(h_words + 64);  // 4*48 bit-pairs

    const int tid  = threadIdx.x;
    const int wid  = tid >> 5;
    const int lane = tid & 31;

    const int base = blockIdx.x * ROWS_PER_CTA;
    const int rcnt = min(ROWS_PER_CTA, NTT - base);
    if (rcnt <= 0) return;

    // Load w into smem at pitch 92; pad column + pad row zeroed.
    for (int idx = tid; idx < W_FLOATS; idx += 512) w_s[idx] = 0.f;
    __syncthreads();
    for (int idx = tid; idx < 512 * 88; idx += 512) {
        int j = idx / 88, i = idx - j * 88;
        w_s[j * WPITCH + i] = w[idx];
    }
    __syncthreads();

    for (int b0 = 0; b0 < rcnt; b0 += 4) {
        const int row0 = base + b0;

        // ---- per-batch bias loads ----
        for (int idx = tid; idx < 4 * 512; idx += 512) {
            int r = idx >> 9, k = idx & 511;
            int row = row0 + r;
            bht_s[idx] = (row < NTT) ? bht_g[(size_t)row * HDIM + k] : 0.f;
        }
        for (int idx = tid; idx < 4 * 96; idx += 512) {
            int r = idx / 96, i = idx - r * 96;
            int row = row0 + r;
            bvt_s[idx] = (row < NTT && i < VDIM) ? bvt_g[(size_t)row * VDIM + i] : 0.f;
        }

        // ---- init v packed floats + vis words from visible[row+1] ----
        if (wid < 4) {
            const int r = wid;
            const int row = row0 + r;
            const bool valid = (row < NTT);
            float* vt = (r < 2) ? (float*)v01 : (float*)v23;
            const int half = r & 1;
#pragma unroll
            for (int it = 0; it < 3; it++) {
                int i = it * 32 + lane;
                bool bit = valid && (i < VDIM) &&
                           (visible[(size_t)(row + 1) * VDIM + i] > 0.5f);
                unsigned m = __ballot_sync(0xffffffffu, bit);
                if (lane == 0) vis_w[r * 3 + it] = m;
                if (i < VDIM) vt[2 * i + half] = bit ? 1.f : 0.f;
            }
        }
        __syncthreads();

        for (int s = 0; s < GS; s++) {
            // ---------- h-phase: thread j = tid, dense FFMA2, 4 rows ----------
            {
                const int j = tid;
                const float4* wr4 = (const float4*)(w_s + j * WPITCH);
                ull acc01 = 0ull, acc23 = 0ull;
#pragma unroll
                for (int q = 0; q < 22; q++) {
                    float4 wv = wr4[q];
                    ulonglong2 a01 = *(const ulonglong2*)(v01 + q * 4);
                    ulonglong2 b01 = *(const ulonglong2*)(v01 + q * 4 + 2);
                    ulonglong2 a23 = *(const ulonglong2*)(v23 + q * 4);
                    ulonglong2 b23 = *(const ulonglong2*)(v23 + q * 4 + 2);
                    ull w0 = dup2_(wv.x), w1 = dup2_(wv.y);
                    ull w2 = dup2_(wv.z), w3 = dup2_(wv.w);
                    acc01 = fma2_(w0, a01.x, acc01); acc23 = fma2_(w0, a23.x, acc23);
                    acc01 = fma2_(w1, a01.y, acc01); acc23 = fma2_(w1, a23.y, acc23);
                    acc01 = fma2_(w2, b01.x, acc01); acc23 = fma2_(w2, b23.x, acc23);
                    acc01 = fma2_(w3, b01.y, acc01); acc23 = fma2_(w3, b23.y, acc23);
                }
                float accs[4] = {lo2_(acc01), hi2_(acc01), lo2_(acc23), hi2_(acc23)};
#pragma unroll
                for (int r = 0; r < 4; r++) {
                    const int row = row0 + r;
                    float rh = (row < NTT)
                             ? rand_h[((size_t)row * GS + s) * HDIM + j] : 2.f;
                    float pre = accs[r] + bht_s[r * 512 + j];
                    float sg = 1.f / (1.f + expf(-pre));
                    unsigned m = __ballot_sync(0xffffffffu, sg > rh);
                    if (lane == 0) h_words[r * 16 + wid] = m;
                }
            }
            __syncthreads();

            // ---------- build h lists (warp r) ----------
            if (wid < 4) {
                const int r = wid;
                unsigned wd = (lane < 16) ? h_words[r * 16 + lane] : 0u;
                unsigned c = __popc(wd);
                unsigned sc = c;
#pragma unroll
                for (int oo = 1; oo < 16; oo <<= 1) {
                    unsigned v = __shfl_up_sync(0xffffffffu, sc, oo);
                    if (lane >= oo) sc += v;
                }
                unsigned total = __shfl_sync(0xffffffffu, sc, 15);
                if (lane < 16) {
                    unsigned pos = sc - c;
                    unsigned x = wd;
                    while (x) {
                        int bb = __ffs(x) - 1;
                        h_list[r * 520 + pos++] = (lane * 32 + bb) * (WPITCH * 4);
                        x &= x - 1;
                    }
                }
                if (lane == 0) {
                    unsigned t4 = (total + 3) & ~3u;
                    for (unsigned q = total; q < t4; q++) h_list[r * 520 + q] = PAD_HOFF;
                    h_cnt[r] = t4;
                }
            }
            __syncthreads();

            // ---------- v-phase: 176 threads, column pairs, add2 ----------
            if (tid < 176) {
                const int r  = tid / 44;
                const int i2 = tid - r * 44;
                const int i0 = i2 * 2;
                const int row = row0 + r;
                const bool act = (row < NTT);
                float bv0 = bvt_s[r * 96 + i0];
                float bv1 = bvt_s[r * 96 + i0 + 1];
                float rv0 = act ? rand_v[((size_t)row * GS + s) * VDIM + i0] : 2.f;
                float rv1 = act ? rand_v[((size_t)row * GS + s) * VDIM + i0 + 1] : 2.f;
                const char* wb = (const char*)w_s + i0 * 4;
                ull acc2 = 0ull;
                const int n = (int)h_cnt[r];
                const int* lst = h_list + r * 520;
                for (int m = 0; m < n; m += 4) {
                    int4 o4 = *(const int4*)(lst + m);
                    acc2 = add2_(acc2, *(const ull*)(wb + o4.x));
                    acc2 = add2_(acc2, *(const ull*)(wb + o4.y));
                    acc2 = add2_(acc2, *(const ull*)(wb + o4.z));
                    acc2 = add2_(acc2, *(const ull*)(wb + o4.w));
                }
                float p0 = lo2_(acc2) + bv0;
                float p1 = hi2_(acc2) + bv1;
                float s0 = 1.f / (1.f + expf(-p0));
                float s1 = 1.f / (1.f + expf(-p1));
                int bb0 = (s0 > rv0) ? 1 : 0;
                int bb1 = (s1 > rv1) ? 1 : 0;
                float* vt = (r < 2) ? (float*)v01 : (float*)v23;
                const int half = r & 1;
                vt[2 * i0 + half]       = (float)bb0;
                vt[2 * (i0 + 1) + half] = (float)bb1;
                vb[r * 48 + i2] = (unsigned char)(bb0 | (bb1 << 1));
            }
            __syncthreads();
        }

        // ---- mse: popcount(v ^ v_seq)/88 from vb + vis words ----
        if (wid < 4) {
            const int r = wid, row = row0 + r;
            if (row < NTT) {
                unsigned d = 0;
#pragma unroll
                for (int it = 0; it < 3; it++) {
                    int i = it * 32 + lane;
                    unsigned bit = 0;
                    if (i < VDIM) bit = (vb[r * 48 + (i >> 1)] >> (i & 1)) & 1u;
                    unsigned m = __ballot_sync(0xffffffffu, bit != 0);
                    d += __popc(m ^ vis_w[r * 3 + it]);
                }
                if (lane == 0) out[1 + row] = (float)d / 88.0f;
            }
        }
        __syncthreads();
    }
}

// ---------------------------------------------------------------------------
// Small utility kernels (unchanged)
// ---------------------------------------------------------------------------
__global__ void ce_partial_kernel(const float* __restrict__ visible,
                                  const float* __restrict__ bvt, double* __restrict__ out) {
    __shared__ double sd[256];
    double s = 0.0;
    const int n = NTT * VDIM;
    for (int idx = blockIdx.x * 256 + threadIdx.x; idx < n; idx += gridDim.x * 256) {
        float x = bvt[idx];
        float y = 1.f / (1.f + expf(-x));
        float v = visible[idx + VDIM];
        float term = -(v * logf(1e-6f + y) + (1.f - v) * logf(1e-6f + 1.f - y));
        s += (double)term;
    }
    sd[threadIdx.x] = s;
    __syncthreads();
    for (int o = 128; o; o >>= 1) {
        if (threadIdx.x < o) sd[threadIdx.x] += sd[threadIdx.x + o];
        __syncthreads();
    }
    if (threadIdx.x == 0) out[blockIdx.x] = sd[0];
}

__global__ void sqsum_kernel(const float* __restrict__ x, int n, double* __restrict__ out) {
    __shared__ double sd[256];
    double s = 0.0;
    for (int i = blockIdx.x * 256 + threadIdx.x; i < n; i += gridDim.x * 256) {
        float f = x[i];
        s += (double)f * (double)f;
    }
    sd[threadIdx.x] = s;
    __syncthreads();
    for (int o = 128; o; o >>= 1) {
        if (threadIdx.x < o) sd[threadIdx.x] += sd[threadIdx.x + o];
        __syncthreads();
    }
    if (threadIdx.x == 0) out[blockIdx.x] = sd[0];
}

__global__ void finalize_kernel(const double* __restrict__ ce,
                                const double* __restrict__ n2uv,
                                const double* __restrict__ n2uh,
                                float* __restrict__ out) {
    __shared__ double s[256];
    const int t = threadIdx.x;
    s[t] = ce[t];
    __syncthreads();
    for (int o = 128; o; o >>= 1) { if (t < o) s[t] += s[t + o]; __syncthreads(); }
    double ce_sum = s[0];
    __syncthreads();
    s[t] = (t < 64) ? n2uv[t] : 0.0;
    __syncthreads();
    for (int o = 128; o; o >>= 1) { if (t < o) s[t] += s[t + o]; __syncthreads(); }
    double suv = s[0];
    __syncthreads();
    s[t] = (t < 64) ? n2uh[t] : 0.0;
    __syncthreads();
    for (int o = 128; o; o >>= 1) { if (t < o) s[t] += s[t + o]; __syncthreads(); }
    double suh = s[0];
    if (t == 0) {
        double reg = 0.2 * (sqrt(suv) + sqrt(suh));
        out[0]      = (float)(ce_sum / (double)TSTEPS + reg);
        out[TSTEPS] = (float)reg;
    }
}

// ---------------------------------------------------------------------------
// Launch (serial pipeline — each stage at full boost)
// ---------------------------------------------------------------------------
extern "C" void kernel_launch(void* const* d_in, const int* in_sizes, int n_in,
                              void* d_out, int out_size) {
    const float* visible = (const float*)d_in[0];
    const float* rand_h  = (const float*)d_in[1];
    const float* rand_v  = (const float*)d_in[2];
    const float* w       = (const float*)d_in[3];
    const float* wuu     = (const float*)d_in[4];
    const float* wuv     = (const float*)d_in[5];
    const float* wuh     = (const float*)d_in[6];
    const float* wvu     = (const float*)d_in[7];
    const float* bv      = (const float*)d_in[8];
    const float* bh      = (const float*)d_in[9];
    const float* bu      = (const float*)d_in[10];
    const float* u0      = (const float*)d_in[11];
    float* out = (float*)d_out;

    void *pa, *pu, *pbh, *pbv, *pce, *pnuv, *pnuh;
    cudaGetSymbolAddress(&pa,   g_a);
    cudaGetSymbolAddress(&pu,   g_uprev);
    cudaGetSymbolAddress(&pbh,  g_bht);
    cudaGetSymbolAddress(&pbv,  g_bvt);
    cudaGetSymbolAddress(&pce,  g_ce);
    cudaGetSymbolAddress(&pnuv, g_n2uv);
    cudaGetSymbolAddress(&pnuh, g_n2uh);

    // 1) a[t] = v_seq[t] @ wvu^T + bu
    {
        dim3 g((NTT + 127) / 128, (RDIM + 63) / 64);
        gemm2_nt<8><<<g, 256>>>(visible + VDIM, VDIM, wvu, VDIM,
                                bu, (float*)pa, RDIM, NTT, RDIM, VDIM);
    }

    // 2) sequential recurrence -> u_prev
    recur_kernel<<<8, 512>>>(wuu, (const float*)pa, u0, (float*)pu);

    // 3) bh_t = u_prev @ wuh^T + bh ; bv_t = u_prev @ wuv^T + bv
    {
        dim3 g((NTT + 127) / 128, (HDIM + 63) / 64);
        gemm2_nt<8><<<g, 256>>>((const float*)pu, RDIM, wuh, RDIM,
                                bh, (float*)pbh, HDIM, NTT, HDIM, RDIM);
        dim3 g2((NTT + 63) / 64, (VDIM + 63) / 64);
        gemm2_nt<4><<<g2, 256>>>((const float*)pu, RDIM, wuv, RDIM,
                                 bv, (float*)pbv, VDIM, NTT, VDIM, RDIM);
    }

    // 4) fused Gibbs (20 steps) + mse, one launch
    {
        const int smem = W_FLOATS * 4 + (4 * 512 + 4 * 96) * 4 + 2 * 96 * 8
                       + 4 * 520 * 4 + (4 + 12 + 64) * 4 + 4 * 48 + 256;
        cudaFuncSetAttribute(gibbs_fused,
                             cudaFuncAttributeMaxDynamicSharedMemorySize, smem);
        const int grid = (NTT + ROWS_PER_CTA - 1) / ROWS_PER_CTA;  // 147
        gibbs_fused<<<grid, 512, smem>>>(visible, rand_h, rand_v, w,
                                         (const float*)pbh, (const float*)pbv, out);
    }

    // 5) reductions
    ce_partial_kernel<<<256, 256>>>(visible, (const float*)pbv, (double*)pce);
    sqsum_kernel<<<64, 256>>>(wuv, VDIM * RDIM, (double*)pnuv);
    sqsum_kernel<<<64, 256>>>(wuh, HDIM * RDIM, (double*)pnuh);
    finalize_kernel<<<1, 256>>>((const double*)pce, (const double*)pnuv,
                                (const double*)pnuh, out);
}